// round 10
// baseline (speedup 1.0000x reference)
#include <cuda_runtime.h>
#include <cuda_bf16.h>

#define T_STEPS 1024
#define BATCH   256
#define HID     512
#define NBLK    128
#define THREADS 512
#define NLEAF   16

// 2D tiling: 4 batch-slices x 32 unit-slices
#define MB       64      // batches per block
#define NG       64      // gate columns per block (16 units x 4 gates)
#define UNITS    16

// smem layout (bytes): only W + params now
#define WPITCH    72                          // bf16 per k-row (64 + 8 pad) = 144 B
#define WBYTES    (HID * WPITCH * 2)          // 73728 per W matrix
#define OFF_WHI   0
#define OFF_WLO   WBYTES                      // 73728
#define OFF_P     (2 * WBYTES)                // 147456
#define SMEM_TOTAL (OFF_P + 1024)             // 148480

// h in MMA A-fragment layout: [buf][mi][mt][kt][lane] -> 32B record
// record = { a0,a1,a2,a3 bf16-pairs (hi) : 16B | same (lo) : 16B }
__device__ __nv_bfloat16 g_hf[2][4][4][32][32][16];   // 2 MB
__device__ float g_hplain[BATCH * HID];               // final h, fp32
__device__ float g_zxT[64 * BATCH];
__device__ float g_zeT[16 * BATCH];
__device__ unsigned int g_leaf[NLEAF];
__device__ unsigned int g_master;
__device__ unsigned int g_gen;
__device__ unsigned int g_gcnt[4 * 32];
__device__ unsigned int g_ggen[4 * 32];

// ---------- helpers ----------
__device__ __forceinline__ unsigned s2u(const void* p) {
    unsigned r;
    asm("{ .reg .u64 t; cvta.to.shared.u64 t, %1; cvt.u32.u64 %0, t; }"
        : "=r"(r) : "l"(p));
    return r;
}

__device__ __forceinline__ void mma16816(float* d, const unsigned* a, const unsigned* b) {
    asm volatile(
        "mma.sync.aligned.m16n8k16.row.col.f32.bf16.bf16.f32 "
        "{%0,%1,%2,%3}, {%4,%5,%6,%7}, {%8,%9}, {%0,%1,%2,%3};"
        : "+f"(d[0]), "+f"(d[1]), "+f"(d[2]), "+f"(d[3])
        : "r"(a[0]), "r"(a[1]), "r"(a[2]), "r"(a[3]), "r"(b[0]), "r"(b[1]));
}

__device__ __forceinline__ void ldsm_x4t(unsigned* r, unsigned addr) {
    asm volatile("ldmatrix.sync.aligned.m8n8.x4.trans.shared.b16 {%0,%1,%2,%3}, [%4];"
                 : "=r"(r[0]), "=r"(r[1]), "=r"(r[2]), "=r"(r[3]) : "r"(addr));
}

__device__ __forceinline__ float sigf(float v) {
    return __fdividef(1.0f, 1.0f + __expf(-v));
}
__device__ __forceinline__ float tanh_fast(float v) {
    return __fdividef(2.0f, 1.0f + __expf(-2.0f * v)) - 1.0f;
}

// Full-grid hierarchical barrier (128 blocks: 16 leaves x 8)
__device__ __forceinline__ void gsyncF(int bid) {
    __syncthreads();
    if (threadIdx.x == 0) {
        volatile unsigned int* genp = &g_gen;
        unsigned int g = *genp;
        __threadfence();
        bool release = false;
        if (atomicAdd(&g_leaf[bid & (NLEAF - 1)], 1u) == (NBLK / NLEAF) - 1u) {
            if (atomicAdd(&g_master, 1u) == NLEAF - 1u) {
                #pragma unroll
                for (int i = 0; i < NLEAF; i++) g_leaf[i] = 0u;
                g_master = 0u;
                __threadfence();
                *genp = g + 1u;
                release = true;
            }
        }
        if (!release) {
            while (*genp == g) { }
        }
    }
    __syncthreads();
}

// Per-group barrier: only the 32 blocks sharing batch-slice mi.
__device__ __forceinline__ void gsyncG(int mi) {
    __syncthreads();
    if (threadIdx.x == 0) {
        volatile unsigned int* genp = &g_ggen[mi * 32];
        unsigned int g = *genp;
        __threadfence();
        if (atomicAdd(&g_gcnt[mi * 32], 1u) == 31u) {
            atomicExch(&g_gcnt[mi * 32], 0u);
            __threadfence();
            *genp = g + 1u;
        } else {
            while (*genp == g) { }
        }
    }
    __syncthreads();
}

// ---------- main persistent kernel ----------
extern "C" __global__ void __launch_bounds__(THREADS, 1)
lstm_persist(const float* __restrict__ x, const float* __restrict__ a,
             const float* __restrict__ y,
             const float* __restrict__ W_ih, const float* __restrict__ W_hh,
             const float* __restrict__ b_ih, const float* __restrict__ b_hh,
             const float* __restrict__ W_eta, const float* __restrict__ b_eta,
             const float* __restrict__ W_xi,  const float* __restrict__ b_xi,
             const float* __restrict__ W_zeta, const float* __restrict__ b_zeta,
             float* __restrict__ out) {
    extern __shared__ char smem[];
    __nv_bfloat16* sWhi = (__nv_bfloat16*)(smem + OFF_WHI);
    __nv_bfloat16* sWlo = (__nv_bfloat16*)(smem + OFF_WLO);
    float* swx = (float*)(smem + OFF_P);
    float* swa = swx + 64;
    float* swy = swx + 128;
    float* sbb = swx + 192;
    const unsigned sb = s2u(smem);

    const int tid  = threadIdx.x;
    const int lane = tid & 31;
    const int w    = tid >> 5;       // 16 warps
    const int bid  = blockIdx.x;
    const int mi   = bid >> 5;       // batch slice 0..3
    const int ni   = bid & 31;       // unit slice 0..31
    const int wm   = w & 3;          // m-tile: rows 16*wm .. +15
    const int wn   = w >> 2;         // n-group: cols 16*wn (two 8-wide tiles)

    // ---- W tile into smem, K-MAJOR: sW[k][j], pitch WPITCH bf16 ----
    for (int idx = tid; idx < NG * HID; idx += THREADS) {
        int j = idx >> 9, k = idx & 511;
        int row = (j & 3) * HID + ni * UNITS + (j >> 2); // gate row in W_hh
        float v = W_hh[row * HID + k];
        __nv_bfloat16 hi = __float2bfloat16(v);
        sWhi[k * WPITCH + j] = hi;
        sWlo[k * WPITCH + j] = __float2bfloat16(v - __bfloat162float(hi));
    }
    if (tid < NG) {
        int row = (tid & 3) * HID + ni * UNITS + (tid >> 2);
        swx[tid] = W_ih[row * 3 + 0];
        swa[tid] = W_ih[row * 3 + 1];
        swy[tid] = W_ih[row * 3 + 2];
        sbb[tid] = b_ih[row] + b_hh[row];
    }

    // ---- zero fragment buffer 0 for our batch slice (group-cooperative) ----
    {
        uint4 z = make_uint4(0u, 0u, 0u, 0u);
        uint4* Z = (uint4*)(&g_hf[0][mi][0][0][0][0]);   // 131072 B = 8192 uint4
        for (int i = ni * THREADS + tid; i < 8192; i += 32 * THREADS) Z[i] = z;
    }
    gsyncG(mi);

    // epilogue ownership
    const bool act = ((lane & 1) == 0);
    const int qr  = lane >> 2;              // 0..7
    const int hb  = (lane & 3) >> 1;        // 0 or 1 (unit low bit / bf16 half)
    const int r0  = 16 * wm + qr;           // local batch rows
    const int b0g = mi * MB + r0;
    const int b1g = b0g + 8;
    float cst[2][2] = {{0.f, 0.f}, {0.f, 0.f}};

    // B ldmatrix base (k-major W), same as round 9
    const unsigned bbase = (unsigned)((lane & 15) * (WPITCH * 2)
                                      + (16 * wn + ((lane >> 4) & 1) * 8) * 2);

    int cur = 0;
    for (int s = 0; s < T_STEPS; s++) {
        const int t = T_STEPS - 1 - s;

        // A fragments straight from global (fragment-layout h).
        // stride per kt = 32 lanes * 32 B = 1024 B
        const char* Ab = (const char*)(&g_hf[cur][mi][wm][0][lane][0]);

        uint4 bh[4], bl[4];
        #pragma unroll
        for (int p = 0; p < 4; p++) {
            bh[p] = __ldcg((const uint4*)(Ab + p * 1024));
            bl[p] = __ldcg((const uint4*)(Ab + p * 1024 + 16));
        }

        // epilogue inputs (latency hidden under GEMM)
        float x0 = __ldg(&x[t * BATCH + b0g]);
        float a0 = __ldg(&a[t * BATCH + b0g]);
        float y0 = __ldg(&y[t * BATCH + b0g]);
        float x1 = __ldg(&x[t * BATCH + b1g]);
        float a1 = __ldg(&a[t * BATCH + b1g]);
        float y1 = __ldg(&y[t * BATCH + b1g]);

        float acc[2][4] = {{0.f, 0.f, 0.f, 0.f}, {0.f, 0.f, 0.f, 0.f}};

        #pragma unroll 8
        for (int kt = 0; kt < 32; kt++) {
            const int slot = kt & 3;
            unsigned ahi[4], alo[4];
            { uint4 v = bh[slot]; ahi[0]=v.x; ahi[1]=v.y; ahi[2]=v.z; ahi[3]=v.w; }
            { uint4 v = bl[slot]; alo[0]=v.x; alo[1]=v.y; alo[2]=v.z; alo[3]=v.w; }
            const int pf = (kt + 4) & 31;   // wrap: harmless redundant reload
            bh[slot] = __ldcg((const uint4*)(Ab + pf * 1024));
            bl[slot] = __ldcg((const uint4*)(Ab + pf * 1024 + 16));

            unsigned bhi[4], blo[4];
            const unsigned kb = bbase + (unsigned)(kt * (16 * WPITCH * 2));
            ldsm_x4t(bhi, sb + OFF_WHI + kb);
            ldsm_x4t(blo, sb + OFF_WLO + kb);
            mma16816(acc[0], ahi, bhi + 0);
            mma16816(acc[1], ahi, bhi + 2);
            mma16816(acc[0], ahi, blo + 0);
            mma16816(acc[1], ahi, blo + 2);
            mma16816(acc[0], alo, bhi + 0);
            mma16816(acc[1], alo, bhi + 2);
        }

        // ---- epilogue: xproj add, fragment exchange, gates, h store ----
        #pragma unroll
        for (int nt = 0; nt < 2; nt++) {
            int ce = 16 * wn + nt * 8 + 2 * (lane & 3);
            int co = ce + 1;
            float wxe = swx[ce], wae = swa[ce], wye = swy[ce], bbe = sbb[ce];
            float wxo = swx[co], wao = swa[co], wyo = swy[co], bbo = sbb[co];
            acc[nt][0] += fmaf(wxe, x0, fmaf(wae, a0, fmaf(wye, y0, bbe)));
            acc[nt][1] += fmaf(wxo, x0, fmaf(wao, a0, fmaf(wyo, y0, bbo)));
            acc[nt][2] += fmaf(wxe, x1, fmaf(wae, a1, fmaf(wye, y1, bbe)));
            acc[nt][3] += fmaf(wxo, x1, fmaf(wao, a1, fmaf(wyo, y1, bbo)));
        }

        float gg[2][4];
        #pragma unroll
        for (int nt = 0; nt < 2; nt++)
            #pragma unroll
            for (int i = 0; i < 4; i++)
                gg[nt][i] = __shfl_xor_sync(0xffffffffu, acc[nt][i], 1);

        if (act) {
            // writes target record [cur^1][mi][wm][ni][flane]
            char* Hb = (char*)(&g_hf[cur ^ 1][mi][wm][ni][0][0]);
            const int regbase = 2 * (wn >> 1);
            #pragma unroll
            for (int nt = 0; nt < 2; nt++) {
                const int flane = qr * 4 + 2 * (wn & 1) + nt;
                #pragma unroll
                for (int rr = 0; rr < 2; rr++) {
                    float iv = acc[nt][2 * rr + 0];
                    float fv = acc[nt][2 * rr + 1];
                    float gv = gg[nt][2 * rr + 0];
                    float ov = gg[nt][2 * rr + 1];
                    float cn = sigf(fv) * cst[nt][rr] + sigf(iv) * tanh_fast(gv);
                    cst[nt][rr] = cn;
                    float h = sigf(ov) * tanh_fast(cn);
                    unsigned off = (unsigned)(flane * 32 + (regbase + rr) * 4 + hb * 2);
                    __nv_bfloat16 hh = __float2bfloat16(h);
                    *(__nv_bfloat16*)(Hb + off)      = hh;
                    *(__nv_bfloat16*)(Hb + off + 16) = __float2bfloat16(h - __bfloat162float(hh));
                    if (s == T_STEPS - 1) {
                        int kg = ni * UNITS + 4 * wn + 2 * nt + hb;
                        int bg = rr ? b1g : b0g;
                        g_hplain[bg * HID + kg] = h;
                    }
                }
            }
        }
        gsyncG(mi);
        cur ^= 1;
    }

    // all four groups must finish before heads read full h
    gsyncF(bid);

    const int b = tid;

    // Phase A: zx columns (blocks 0..63), ze logits (blocks 64..79)
    if (b < BATCH) {
        if (bid < 64) {
            const int m = bid;
            float acc = b_xi[m];
            const float* wm_ = W_xi + m * HID;
            #pragma unroll 8
            for (int k = 0; k < HID; k++)
                acc = fmaf(g_hplain[b * HID + k], __ldg(&wm_[k]), acc);
            out[b * 64 + m] = acc;                  // zx: [B][64] at 0
            g_zxT[m * BATCH + b] = acc;
        } else if (bid < 80) {
            const int e = bid - 64;
            float acc = b_eta[e];
            const float* we = W_eta + e * HID;
            #pragma unroll 8
            for (int k = 0; k < HID; k++)
                acc = fmaf(g_hplain[b * HID + k], __ldg(&we[k]), acc);
            g_zeT[e * BATCH + b] = acc;
        }
    }
    gsyncF(bid);

    // Phase B: zy columns (blocks 0..63), ze softmax (block 64)
    if (b < BATCH) {
        if (bid < 64) {
            const int m = bid;
            float acc = b_zeta[m];
            const float* wz = W_zeta + m * (HID + 64);
            #pragma unroll 8
            for (int k = 0; k < HID; k++)
                acc = fmaf(g_hplain[b * HID + k], __ldg(&wz[k]), acc);
            #pragma unroll
            for (int j = 0; j < 64; j++)
                acc = fmaf(g_zxT[j * BATCH + b], __ldg(&wz[HID + j]), acc);
            out[16384 + b * 64 + m] = acc;          // zy: [B][64] at 16384
        } else if (bid == 64) {
            float l[16];
            float mx = -1e30f;
            #pragma unroll
            for (int e = 0; e < 16; e++) {
                l[e] = g_zeT[e * BATCH + b];
                mx = fmaxf(mx, l[e]);
            }
            float ssum = 0.0f;
            #pragma unroll
            for (int e = 0; e < 16; e++) { l[e] = __expf(l[e] - mx); ssum += l[e]; }
            float inv = __fdividef(1.0f, ssum);
            #pragma unroll
            for (int e = 0; e < 16; e++)
                out[32768 + b * 16 + e] = l[e] * inv;   // ze: [B][16] at 32768
        }
    }
}

extern "C" void kernel_launch(void* const* d_in, const int* in_sizes, int n_in,
                              void* d_out, int out_size) {
    const float* x      = (const float*)d_in[0];
    const float* a      = (const float*)d_in[1];
    const float* y      = (const float*)d_in[2];
    const float* W_ih   = (const float*)d_in[3];
    const float* W_hh   = (const float*)d_in[4];
    const float* b_ih   = (const float*)d_in[5];
    const float* b_hh   = (const float*)d_in[6];
    const float* W_eta  = (const float*)d_in[7];
    const float* b_eta  = (const float*)d_in[8];
    const float* W_xi   = (const float*)d_in[9];
    const float* b_xi   = (const float*)d_in[10];
    const float* W_zeta = (const float*)d_in[11];
    const float* b_zeta = (const float*)d_in[12];

    cudaFuncSetAttribute(lstm_persist,
                         cudaFuncAttributeMaxDynamicSharedMemorySize, SMEM_TOTAL);
    lstm_persist<<<NBLK, THREADS, SMEM_TOTAL>>>(
        x, a, y, W_ih, W_hh, b_ih, b_hh,
        W_eta, b_eta, W_xi, b_xi, W_zeta, b_zeta,
        (float*)d_out);
}

// round 11
// speedup vs baseline: 1.1845x; 1.1845x over previous
#include <cuda_runtime.h>
#include <cuda_bf16.h>

#define T_STEPS 1024
#define BATCH   256
#define HID     512
#define NBLK    128
#define THREADS 512

// 2D tiling: 4 batch-slices x 32 unit-slices
#define MB       64      // batches per block
#define NG       64      // gate columns per block (16 units x 4 gates)
#define UNITS    16

// W smem (k-major, proven layout)
#define WPITCH    72                          // bf16 per k-row (64 + 8 pad) = 144 B
#define WBYTES    (HID * WPITCH * 2)          // 73728 per W matrix
#define OFF_WHI   0
#define OFF_WLO   WBYTES

// A staging: 8 chunks of 64 k, 3 buffers, per-row 144B (conflict-free ldsm)
#define CHUNKS   8
#define CKK      64
#define AROWB    144
#define AMAT     (MB * AROWB)                 // 9216 per matrix (hi or lo)
#define ABUF     (2 * AMAT)                   // 18432 per buffer
#define NBUF     3
#define OFF_A    (2 * WBYTES)                 // 147456
#define OFF_P    (OFF_A + NBUF * ABUF)        // 202752
#define SMEM_TOTAL (OFF_P + 1024)             // 203776

// Persistent device state
__device__ __nv_bfloat16 g_hhi[2][BATCH * HID];
__device__ __nv_bfloat16 g_hlo[2][BATCH * HID];
__device__ float g_zxT[64 * BATCH];
__device__ float g_zeT[16 * BATCH];
__device__ unsigned int g_gcnt4[4 * 32];   // per-group monotonic counters (128B apart)
__device__ unsigned int g_fcnt;            // full-grid monotonic counter

// ---------- helpers ----------
__device__ __forceinline__ unsigned s2u(const void* p) {
    unsigned r;
    asm("{ .reg .u64 t; cvta.to.shared.u64 t, %1; cvt.u32.u64 %0, t; }"
        : "=r"(r) : "l"(p));
    return r;
}

__device__ __forceinline__ void mma16816(float* d, const unsigned* a, const unsigned* b) {
    asm volatile(
        "mma.sync.aligned.m16n8k16.row.col.f32.bf16.bf16.f32 "
        "{%0,%1,%2,%3}, {%4,%5,%6,%7}, {%8,%9}, {%0,%1,%2,%3};"
        : "+f"(d[0]), "+f"(d[1]), "+f"(d[2]), "+f"(d[3])
        : "r"(a[0]), "r"(a[1]), "r"(a[2]), "r"(a[3]), "r"(b[0]), "r"(b[1]));
}

__device__ __forceinline__ void ldsm_x4(unsigned* r, unsigned addr) {
    asm volatile("ldmatrix.sync.aligned.m8n8.x4.shared.b16 {%0,%1,%2,%3}, [%4];"
                 : "=r"(r[0]), "=r"(r[1]), "=r"(r[2]), "=r"(r[3]) : "r"(addr));
}
__device__ __forceinline__ void ldsm_x4t(unsigned* r, unsigned addr) {
    asm volatile("ldmatrix.sync.aligned.m8n8.x4.trans.shared.b16 {%0,%1,%2,%3}, [%4];"
                 : "=r"(r[0]), "=r"(r[1]), "=r"(r[2]), "=r"(r[3]) : "r"(addr));
}

__device__ __forceinline__ void cpa16(unsigned dst, const void* src) {
    asm volatile("cp.async.cg.shared.global [%0], [%1], 16;"
                 :: "r"(dst), "l"(src) : "memory");
}
__device__ __forceinline__ void cpa_commit() {
    asm volatile("cp.async.commit_group;" ::: "memory");
}
template<int N> __device__ __forceinline__ void cpa_wait() {
    asm volatile("cp.async.wait_group %0;" :: "n"(N) : "memory");
}

__device__ __forceinline__ void barwm(int wm) {
    asm volatile("bar.sync %0, 128;" :: "r"(1 + wm) : "memory");
}

__device__ __forceinline__ float sigf(float v) {
    return __fdividef(1.0f, 1.0f + __expf(-v));
}
__device__ __forceinline__ float tanh_fast(float v) {
    return __fdividef(2.0f, 1.0f + __expf(-2.0f * v)) - 1.0f;
}

// Monotonic-counter barrier: red.release arrive, per-warp ld.acquire poll.
__device__ __forceinline__ void arrive_wait(unsigned int* cnt, unsigned target,
                                            int tid, int lane) {
    __syncthreads();                 // all h-stores issued, block gathered
    if (tid == 0) {
        __threadfence();
        asm volatile("red.release.gpu.global.add.u32 [%0], 1;"
                     :: "l"(cnt) : "memory");
    }
    if (lane == 0) {
        unsigned v;
        do {
            asm volatile("ld.acquire.gpu.global.u32 %0, [%1];"
                         : "=r"(v) : "l"(cnt) : "memory");
        } while (v < target);
    }
    __syncwarp();
}

// Stage this wm-group's 16 A-rows for one 64-k chunk (hi+lo), 32B per thread.
__device__ __forceinline__ void copy_chunk(unsigned sb,
                                           const __nv_bfloat16* Ghi,
                                           const __nv_bfloat16* Glo,
                                           int mi, int wm, int gt,
                                           int ck, int buf) {
    int row = gt >> 3;                       // 0..15
    int c16 = gt & 7;                        // 16B unit within 128B row span
    int b   = mi * MB + 16 * wm + row;
    int k0  = ck * CKK + c16 * 8;
    unsigned dst = sb + OFF_A +
                   (unsigned)(buf * ABUF + (16 * wm + row) * AROWB + c16 * 16);
    cpa16(dst,        Ghi + b * HID + k0);
    cpa16(dst + AMAT, Glo + b * HID + k0);
}

// ---------- main persistent kernel ----------
extern "C" __global__ void __launch_bounds__(THREADS, 1)
lstm_persist(const float* __restrict__ x, const float* __restrict__ a,
             const float* __restrict__ y,
             const float* __restrict__ W_ih, const float* __restrict__ W_hh,
             const float* __restrict__ b_ih, const float* __restrict__ b_hh,
             const float* __restrict__ W_eta, const float* __restrict__ b_eta,
             const float* __restrict__ W_xi,  const float* __restrict__ b_xi,
             const float* __restrict__ W_zeta, const float* __restrict__ b_zeta,
             float* __restrict__ out) {
    extern __shared__ char smem[];
    __nv_bfloat16* sWhi = (__nv_bfloat16*)(smem + OFF_WHI);
    __nv_bfloat16* sWlo = (__nv_bfloat16*)(smem + OFF_WLO);
    float* swx = (float*)(smem + OFF_P);
    float* swa = swx + 64;
    float* swy = swx + 128;
    float* sbb = swx + 192;
    const unsigned sb = s2u(smem);

    const int tid  = threadIdx.x;
    const int lane = tid & 31;
    const int w    = tid >> 5;       // 16 warps
    const int bid  = blockIdx.x;
    const int mi   = bid >> 5;       // batch slice 0..3
    const int ni   = bid & 31;       // unit slice 0..31
    const int wm   = w & 3;          // m-tile / wm-group id
    const int wn   = w >> 2;         // n-group
    const int gt   = wn * 32 + lane; // thread index within wm-group (0..127)

    unsigned int* gcnt = &g_gcnt4[mi * 32];
    unsigned gep = 0;

    // ---- W tile into smem, K-MAJOR (proven layout) ----
    for (int idx = tid; idx < NG * HID; idx += THREADS) {
        int j = idx >> 9, k = idx & 511;
        int row = (j & 3) * HID + ni * UNITS + (j >> 2);
        float v = W_hh[row * HID + k];
        __nv_bfloat16 hi = __float2bfloat16(v);
        sWhi[k * WPITCH + j] = hi;
        sWlo[k * WPITCH + j] = __float2bfloat16(v - __bfloat162float(hi));
    }
    if (tid < NG) {
        int row = (tid & 3) * HID + ni * UNITS + (tid >> 2);
        swx[tid] = W_ih[row * 3 + 0];
        swa[tid] = W_ih[row * 3 + 1];
        swy[tid] = W_ih[row * 3 + 2];
        sbb[tid] = b_ih[row] + b_hh[row];
    }

    // ---- zero our slice of h (buffer 0) ----
    for (int e = tid; e < MB * UNITS; e += THREADS) {
        int bl = e >> 4, ku = e & 15;
        int gi = (mi * MB + bl) * HID + ni * UNITS + ku;
        g_hhi[0][gi] = __float2bfloat16(0.0f);
        g_hlo[0][gi] = __float2bfloat16(0.0f);
    }
    arrive_wait(gcnt, 32u * (++gep), tid, lane);

    // epilogue ownership (r9, proven)
    const bool act = ((lane & 1) == 0);
    const int qr  = lane >> 2;
    const int hb  = (lane & 3) >> 1;
    const int r0  = 16 * wm + qr;
    const int b0g = mi * MB + r0;
    const int b1g = b0g + 8;
    float cst[2][2] = {{0.f, 0.f}, {0.f, 0.f}};

    // ldmatrix address components
    const unsigned arow  = (unsigned)((16 * wm + (lane & 15)) * AROWB);
    const unsigned acol  = (unsigned)((lane >> 4) * 16);
    const unsigned bbase = (unsigned)((lane & 15) * (WPITCH * 2)
                                      + (16 * wn + ((lane >> 4) & 1) * 8) * 2);

    int cur = 0;
    for (int s = 0; s < T_STEPS; s++) {
        const int t = T_STEPS - 1 - s;

        const __nv_bfloat16* Ghi = g_hhi[cur];
        const __nv_bfloat16* Glo = g_hlo[cur];

        // prime depth-2 pipeline
        copy_chunk(sb, Ghi, Glo, mi, wm, gt, 0, 0); cpa_commit();
        copy_chunk(sb, Ghi, Glo, mi, wm, gt, 1, 1); cpa_commit();

        float x0 = __ldg(&x[t * BATCH + b0g]);
        float a0 = __ldg(&a[t * BATCH + b0g]);
        float y0 = __ldg(&y[t * BATCH + b0g]);
        float x1 = __ldg(&x[t * BATCH + b1g]);
        float a1 = __ldg(&a[t * BATCH + b1g]);
        float y1 = __ldg(&y[t * BATCH + b1g]);

        float acc[2][4] = {{0.f, 0.f, 0.f, 0.f}, {0.f, 0.f, 0.f, 0.f}};

        #pragma unroll
        for (int ck = 0; ck < CHUNKS; ck++) {
            if (ck < CHUNKS - 1) cpa_wait<1>(); else cpa_wait<0>();
            barwm(wm);               // group-local: copies visible, buf reusable
            if (ck + 2 < CHUNKS) {
                copy_chunk(sb, Ghi, Glo, mi, wm, gt, ck + 2, (ck + 2) % NBUF);
                cpa_commit();
            }

            const unsigned Abase = sb + OFF_A + (unsigned)((ck % NBUF) * ABUF);
            #pragma unroll
            for (int ktl = 0; ktl < 4; ktl++) {
                unsigned ahi[4], alo[4], bhi[4], blo[4];
                unsigned aoff = arow + (unsigned)(ktl * 32) + acol;
                ldsm_x4(ahi, Abase + aoff);
                ldsm_x4(alo, Abase + AMAT + aoff);
                const unsigned kb = bbase
                    + (unsigned)((ck * 4 + ktl) * (16 * WPITCH * 2));
                ldsm_x4t(bhi, sb + OFF_WHI + kb);
                ldsm_x4t(blo, sb + OFF_WLO + kb);
                mma16816(acc[0], ahi, bhi + 0);
                mma16816(acc[1], ahi, bhi + 2);
                mma16816(acc[0], ahi, blo + 0);
                mma16816(acc[1], ahi, blo + 2);
                mma16816(acc[0], alo, bhi + 0);
                mma16816(acc[1], alo, bhi + 2);
            }
        }

        // ---- epilogue (r9, proven): xproj, exchange, gates, h store ----
        #pragma unroll
        for (int nt = 0; nt < 2; nt++) {
            int ce = 16 * wn + nt * 8 + 2 * (lane & 3);
            int co = ce + 1;
            float wxe = swx[ce], wae = swa[ce], wye = swy[ce], bbe = sbb[ce];
            float wxo = swx[co], wao = swa[co], wyo = swy[co], bbo = sbb[co];
            acc[nt][0] += fmaf(wxe, x0, fmaf(wae, a0, fmaf(wye, y0, bbe)));
            acc[nt][1] += fmaf(wxo, x0, fmaf(wao, a0, fmaf(wyo, y0, bbo)));
            acc[nt][2] += fmaf(wxe, x1, fmaf(wae, a1, fmaf(wye, y1, bbe)));
            acc[nt][3] += fmaf(wxo, x1, fmaf(wao, a1, fmaf(wyo, y1, bbo)));
        }

        float gg[2][4];
        #pragma unroll
        for (int nt = 0; nt < 2; nt++)
            #pragma unroll
            for (int i = 0; i < 4; i++)
                gg[nt][i] = __shfl_xor_sync(0xffffffffu, acc[nt][i], 1);

        if (act) {
            __nv_bfloat16* Hhi = g_hhi[cur ^ 1];
            __nv_bfloat16* Hlo = g_hlo[cur ^ 1];
            #pragma unroll
            for (int nt = 0; nt < 2; nt++) {
                int lu = 4 * wn + nt * 2 + ((lane & 3) >> 1);
                int kg = ni * UNITS + lu;
                #pragma unroll
                for (int rr = 0; rr < 2; rr++) {
                    float iv = acc[nt][2 * rr + 0];
                    float fv = acc[nt][2 * rr + 1];
                    float gv = gg[nt][2 * rr + 0];
                    float ov = gg[nt][2 * rr + 1];
                    float cn = sigf(fv) * cst[nt][rr] + sigf(iv) * tanh_fast(gv);
                    cst[nt][rr] = cn;
                    float h = sigf(ov) * tanh_fast(cn);
                    int bg = rr ? b1g : b0g;
                    __nv_bfloat16 hh = __float2bfloat16(h);
                    Hhi[bg * HID + kg] = hh;
                    Hlo[bg * HID + kg] = __float2bfloat16(h - __bfloat162float(hh));
                }
            }
        }
        arrive_wait(gcnt, 32u * (++gep), tid, lane);
        cur ^= 1;
    }

    // all four groups done before heads read full h
    arrive_wait(&g_fcnt, 128u, tid, lane);

    const __nv_bfloat16* Fhi = g_hhi[cur];
    const __nv_bfloat16* Flo = g_hlo[cur];
    const int b = tid;

    // Phase A: zx columns (blocks 0..63), ze logits (blocks 64..79)
    if (b < BATCH) {
        if (bid < 64) {
            const int m = bid;
            float acc = b_xi[m];
            const float* wm_ = W_xi + m * HID;
            #pragma unroll 8
            for (int k = 0; k < HID; k++) {
                float hv = __bfloat162float(Fhi[b * HID + k]) +
                           __bfloat162float(Flo[b * HID + k]);
                acc = fmaf(hv, __ldg(&wm_[k]), acc);
            }
            out[b * 64 + m] = acc;                  // zx: [B][64] at 0
            g_zxT[m * BATCH + b] = acc;
        } else if (bid < 80) {
            const int e = bid - 64;
            float acc = b_eta[e];
            const float* we = W_eta + e * HID;
            #pragma unroll 8
            for (int k = 0; k < HID; k++) {
                float hv = __bfloat162float(Fhi[b * HID + k]) +
                           __bfloat162float(Flo[b * HID + k]);
                acc = fmaf(hv, __ldg(&we[k]), acc);
            }
            g_zeT[e * BATCH + b] = acc;
        }
    }
    arrive_wait(&g_fcnt, 256u, tid, lane);

    // Phase B: zy columns (blocks 0..63), ze softmax (block 64)
    if (b < BATCH) {
        if (bid < 64) {
            const int m = bid;
            float acc = b_zeta[m];
            const float* wz = W_zeta + m * (HID + 64);
            #pragma unroll 8
            for (int k = 0; k < HID; k++) {
                float hv = __bfloat162float(Fhi[b * HID + k]) +
                           __bfloat162float(Flo[b * HID + k]);
                acc = fmaf(hv, __ldg(&wz[k]), acc);
            }
            #pragma unroll
            for (int j = 0; j < 64; j++)
                acc = fmaf(g_zxT[j * BATCH + b], __ldg(&wz[HID + j]), acc);
            out[16384 + b * 64 + m] = acc;          // zy: [B][64] at 16384
        } else if (bid == 64) {
            float l[16];
            float mx = -1e30f;
            #pragma unroll
            for (int e = 0; e < 16; e++) {
                l[e] = g_zeT[e * BATCH + b];
                mx = fmaxf(mx, l[e]);
            }
            float ssum = 0.0f;
            #pragma unroll
            for (int e = 0; e < 16; e++) { l[e] = __expf(l[e] - mx); ssum += l[e]; }
            float inv = __fdividef(1.0f, ssum);
            #pragma unroll
            for (int e = 0; e < 16; e++)
                out[32768 + b * 16 + e] = l[e] * inv;   // ze: [B][16] at 32768
        }
    }
}

// Reset barrier counters after each run so graph replays start from zero.
extern "C" __global__ void reset_counters() {
    int i = threadIdx.x;
    if (i < 128) g_gcnt4[i] = 0u;
    if (i == 128) g_fcnt = 0u;
}

extern "C" void kernel_launch(void* const* d_in, const int* in_sizes, int n_in,
                              void* d_out, int out_size) {
    const float* x      = (const float*)d_in[0];
    const float* a      = (const float*)d_in[1];
    const float* y      = (const float*)d_in[2];
    const float* W_ih   = (const float*)d_in[3];
    const float* W_hh   = (const float*)d_in[4];
    const float* b_ih   = (const float*)d_in[5];
    const float* b_hh   = (const float*)d_in[6];
    const float* W_eta  = (const float*)d_in[7];
    const float* b_eta  = (const float*)d_in[8];
    const float* W_xi   = (const float*)d_in[9];
    const float* b_xi   = (const float*)d_in[10];
    const float* W_zeta = (const float*)d_in[11];
    const float* b_zeta = (const float*)d_in[12];

    cudaFuncSetAttribute(lstm_persist,
                         cudaFuncAttributeMaxDynamicSharedMemorySize, SMEM_TOTAL);
    lstm_persist<<<NBLK, THREADS, SMEM_TOTAL>>>(
        x, a, y, W_ih, W_hh, b_ih, b_hh,
        W_eta, b_eta, W_xi, b_xi, W_zeta, b_zeta,
        (float*)d_out);
    reset_counters<<<1, 256>>>();
}

// round 12
// speedup vs baseline: 1.3385x; 1.1300x over previous
#include <cuda_runtime.h>
#include <cuda_bf16.h>

#define T_STEPS 1024
#define BATCH   256
#define HID     512
#define NBLK    128
#define THREADS 512

// 2D tiling: 4 batch-slices x 32 unit-slices
#define MB       64      // batches per block
#define NG       64      // gate columns per block (16 units x 4 gates)
#define UNITS    16

// W smem (k-major, proven layout) -- only W + params in smem now
#define WPITCH    72                          // bf16 per k-row (64 + 8 pad) = 144 B
#define WBYTES    (HID * WPITCH * 2)          // 73728 per W matrix
#define OFF_WHI   0
#define OFF_WLO   WBYTES
#define OFF_P     (2 * WBYTES)                // 147456
#define SMEM_TOTAL (OFF_P + 1024)             // 148480

// h in MMA A-fragment layout, hi and lo SPLIT (fixes r10 coalescing):
// [buf][mi][mt][kt][lane][8 bf16] -> 16B per lane record; warp kt-load = 512B contig.
__device__ __nv_bfloat16 g_hfhi[2][4][4][32][32][8];   // 512 KB
__device__ __nv_bfloat16 g_hflo[2][4][4][32][32][8];   // 512 KB
__device__ float g_hplain[BATCH * HID];                // final h, fp32
__device__ float g_zxT[64 * BATCH];
__device__ float g_zeT[16 * BATCH];
__device__ unsigned int g_gcnt4[4 * 32];   // per-group monotonic counters (128B apart)
__device__ unsigned int g_fcnt;            // full-grid monotonic counter

// ---------- helpers ----------
__device__ __forceinline__ unsigned s2u(const void* p) {
    unsigned r;
    asm("{ .reg .u64 t; cvta.to.shared.u64 t, %1; cvt.u32.u64 %0, t; }"
        : "=r"(r) : "l"(p));
    return r;
}

__device__ __forceinline__ void mma16816(float* d, const unsigned* a, const unsigned* b) {
    asm volatile(
        "mma.sync.aligned.m16n8k16.row.col.f32.bf16.bf16.f32 "
        "{%0,%1,%2,%3}, {%4,%5,%6,%7}, {%8,%9}, {%0,%1,%2,%3};"
        : "+f"(d[0]), "+f"(d[1]), "+f"(d[2]), "+f"(d[3])
        : "r"(a[0]), "r"(a[1]), "r"(a[2]), "r"(a[3]), "r"(b[0]), "r"(b[1]));
}

__device__ __forceinline__ void ldsm_x4t(unsigned* r, unsigned addr) {
    asm volatile("ldmatrix.sync.aligned.m8n8.x4.trans.shared.b16 {%0,%1,%2,%3}, [%4];"
                 : "=r"(r[0]), "=r"(r[1]), "=r"(r[2]), "=r"(r[3]) : "r"(addr));
}

__device__ __forceinline__ float sigf(float v) {
    return __fdividef(1.0f, 1.0f + __expf(-v));
}
__device__ __forceinline__ float tanh_fast(float v) {
    return __fdividef(2.0f, 1.0f + __expf(-2.0f * v)) - 1.0f;
}

// Monotonic-counter barrier: red.release arrive, per-warp ld.acquire poll.
__device__ __forceinline__ void arrive_wait(unsigned int* cnt, unsigned target,
                                            int tid, int lane) {
    __syncthreads();                 // all h-stores issued, block gathered
    if (tid == 0) {
        __threadfence();
        asm volatile("red.release.gpu.global.add.u32 [%0], 1;"
                     :: "l"(cnt) : "memory");
    }
    if (lane == 0) {
        unsigned v;
        do {
            asm volatile("ld.acquire.gpu.global.u32 %0, [%1];"
                         : "=r"(v) : "l"(cnt) : "memory");
        } while (v < target);
    }
    __syncwarp();
}

// ---------- main persistent kernel ----------
extern "C" __global__ void __launch_bounds__(THREADS, 1)
lstm_persist(const float* __restrict__ x, const float* __restrict__ a,
             const float* __restrict__ y,
             const float* __restrict__ W_ih, const float* __restrict__ W_hh,
             const float* __restrict__ b_ih, const float* __restrict__ b_hh,
             const float* __restrict__ W_eta, const float* __restrict__ b_eta,
             const float* __restrict__ W_xi,  const float* __restrict__ b_xi,
             const float* __restrict__ W_zeta, const float* __restrict__ b_zeta,
             float* __restrict__ out) {
    extern __shared__ char smem[];
    __nv_bfloat16* sWhi = (__nv_bfloat16*)(smem + OFF_WHI);
    __nv_bfloat16* sWlo = (__nv_bfloat16*)(smem + OFF_WLO);
    float* swx = (float*)(smem + OFF_P);
    float* swa = swx + 64;
    float* swy = swx + 128;
    float* sbb = swx + 192;
    const unsigned sb = s2u(smem);

    const int tid  = threadIdx.x;
    const int lane = tid & 31;
    const int w    = tid >> 5;       // 16 warps
    const int bid  = blockIdx.x;
    const int mi   = bid >> 5;       // batch slice 0..3
    const int ni   = bid & 31;       // unit slice 0..31
    const int wm   = w & 3;          // m-tile
    const int wn   = w >> 2;         // n-group

    unsigned int* gcnt = &g_gcnt4[mi * 32];
    unsigned gep = 0;

    // ---- W tile into smem, K-MAJOR (proven layout) ----
    for (int idx = tid; idx < NG * HID; idx += THREADS) {
        int j = idx >> 9, k = idx & 511;
        int row = (j & 3) * HID + ni * UNITS + (j >> 2);
        float v = W_hh[row * HID + k];
        __nv_bfloat16 hi = __float2bfloat16(v);
        sWhi[k * WPITCH + j] = hi;
        sWlo[k * WPITCH + j] = __float2bfloat16(v - __bfloat162float(hi));
    }
    if (tid < NG) {
        int row = (tid & 3) * HID + ni * UNITS + (tid >> 2);
        swx[tid] = W_ih[row * 3 + 0];
        swa[tid] = W_ih[row * 3 + 1];
        swy[tid] = W_ih[row * 3 + 2];
        sbb[tid] = b_ih[row] + b_hh[row];
    }

    // ---- zero fragment buffer 0 for our batch slice (group-cooperative) ----
    {
        uint4 z = make_uint4(0u, 0u, 0u, 0u);
        uint4* Zh = (uint4*)(&g_hfhi[0][mi][0][0][0][0]);   // 64 KB = 4096 uint4
        uint4* Zl = (uint4*)(&g_hflo[0][mi][0][0][0][0]);
        for (int i = ni * THREADS + tid; i < 4096; i += 32 * THREADS) {
            Zh[i] = z;
            Zl[i] = z;
        }
    }
    arrive_wait(gcnt, 32u * (++gep), tid, lane);

    // epilogue ownership (r9/r10, proven)
    const bool act = ((lane & 1) == 0);
    const int qr  = lane >> 2;
    const int hb  = (lane & 3) >> 1;
    const int r0  = 16 * wm + qr;
    const int b0g = mi * MB + r0;
    const int b1g = b0g + 8;
    float cst[2][2] = {{0.f, 0.f}, {0.f, 0.f}};

    // B ldmatrix base (k-major W), proven
    const unsigned bbase = (unsigned)((lane & 15) * (WPITCH * 2)
                                      + (16 * wn + ((lane >> 4) & 1) * 8) * 2);

    int cur = 0;
    for (int s = 0; s < T_STEPS; s++) {
        const int t = T_STEPS - 1 - s;

        // A fragments straight from global (split-array fragment-layout h).
        // one kt = 32 lanes * 16 B = 512 B = 32 uint4; lane record = 16 B.
        const uint4* Ah = (const uint4*)(&g_hfhi[cur][mi][wm][0][lane][0]);
        const uint4* Al = (const uint4*)(&g_hflo[cur][mi][wm][0][lane][0]);

        // depth-4 prefetch ring
        uint4 rh[4], rl[4];
        #pragma unroll
        for (int p = 0; p < 4; p++) {
            rh[p] = __ldcg(Ah + p * 32);
            rl[p] = __ldcg(Al + p * 32);
        }

        // epilogue inputs (latency hidden under GEMM)
        float x0 = __ldg(&x[t * BATCH + b0g]);
        float a0 = __ldg(&a[t * BATCH + b0g]);
        float y0 = __ldg(&y[t * BATCH + b0g]);
        float x1 = __ldg(&x[t * BATCH + b1g]);
        float a1 = __ldg(&a[t * BATCH + b1g]);
        float y1 = __ldg(&y[t * BATCH + b1g]);

        float acc[2][4] = {{0.f, 0.f, 0.f, 0.f}, {0.f, 0.f, 0.f, 0.f}};

        #pragma unroll 8
        for (int kt = 0; kt < 32; kt++) {
            const int slot = kt & 3;
            unsigned ahi[4], alo[4];
            { uint4 v = rh[slot]; ahi[0]=v.x; ahi[1]=v.y; ahi[2]=v.z; ahi[3]=v.w; }
            { uint4 v = rl[slot]; alo[0]=v.x; alo[1]=v.y; alo[2]=v.z; alo[3]=v.w; }
            if (kt + 4 < 32) {
                rh[slot] = __ldcg(Ah + (kt + 4) * 32);
                rl[slot] = __ldcg(Al + (kt + 4) * 32);
            }

            unsigned bhi[4], blo[4];
            const unsigned kb = bbase + (unsigned)(kt * (16 * WPITCH * 2));
            ldsm_x4t(bhi, sb + OFF_WHI + kb);
            ldsm_x4t(blo, sb + OFF_WLO + kb);
            mma16816(acc[0], ahi, bhi + 0);
            mma16816(acc[1], ahi, bhi + 2);
            mma16816(acc[0], ahi, blo + 0);
            mma16816(acc[1], ahi, blo + 2);
            mma16816(acc[0], alo, bhi + 0);
            mma16816(acc[1], alo, bhi + 2);
        }

        // ---- epilogue (proven): xproj, exchange, gates, fragment h store ----
        #pragma unroll
        for (int nt = 0; nt < 2; nt++) {
            int ce = 16 * wn + nt * 8 + 2 * (lane & 3);
            int co = ce + 1;
            float wxe = swx[ce], wae = swa[ce], wye = swy[ce], bbe = sbb[ce];
            float wxo = swx[co], wao = swa[co], wyo = swy[co], bbo = sbb[co];
            acc[nt][0] += fmaf(wxe, x0, fmaf(wae, a0, fmaf(wye, y0, bbe)));
            acc[nt][1] += fmaf(wxo, x0, fmaf(wao, a0, fmaf(wyo, y0, bbo)));
            acc[nt][2] += fmaf(wxe, x1, fmaf(wae, a1, fmaf(wye, y1, bbe)));
            acc[nt][3] += fmaf(wxo, x1, fmaf(wao, a1, fmaf(wyo, y1, bbo)));
        }

        float gg[2][4];
        #pragma unroll
        for (int nt = 0; nt < 2; nt++)
            #pragma unroll
            for (int i = 0; i < 4; i++)
                gg[nt][i] = __shfl_xor_sync(0xffffffffu, acc[nt][i], 1);

        if (act) {
            // write record [cur^1][mi][wm][kt=ni][flane]  (block ni owns kt=ni)
            char* Hh = (char*)(&g_hfhi[cur ^ 1][mi][wm][ni][0][0]);
            char* Hl = (char*)(&g_hflo[cur ^ 1][mi][wm][ni][0][0]);
            const int regbase = 2 * (wn >> 1);
            #pragma unroll
            for (int nt = 0; nt < 2; nt++) {
                const int flane = qr * 4 + 2 * (wn & 1) + nt;
                #pragma unroll
                for (int rr = 0; rr < 2; rr++) {
                    float iv = acc[nt][2 * rr + 0];
                    float fv = acc[nt][2 * rr + 1];
                    float gv = gg[nt][2 * rr + 0];
                    float ov = gg[nt][2 * rr + 1];
                    float cn = sigf(fv) * cst[nt][rr] + sigf(iv) * tanh_fast(gv);
                    cst[nt][rr] = cn;
                    float h = sigf(ov) * tanh_fast(cn);
                    unsigned off = (unsigned)(flane * 16 + (regbase + rr) * 4 + hb * 2);
                    __nv_bfloat16 hh = __float2bfloat16(h);
                    *(__nv_bfloat16*)(Hh + off) = hh;
                    *(__nv_bfloat16*)(Hl + off) = __float2bfloat16(h - __bfloat162float(hh));
                    if (s == T_STEPS - 1) {
                        int kg = ni * UNITS + 4 * wn + 2 * nt + hb;
                        int bg = rr ? b1g : b0g;
                        g_hplain[bg * HID + kg] = h;
                    }
                }
            }
        }
        arrive_wait(gcnt, 32u * (++gep), tid, lane);
        cur ^= 1;
    }

    // all four groups done before heads read full h
    arrive_wait(&g_fcnt, 128u, tid, lane);

    const int b = tid;

    // Phase A: zx columns (blocks 0..63), ze logits (blocks 64..79)
    if (b < BATCH) {
        if (bid < 64) {
            const int m = bid;
            float acc = b_xi[m];
            const float* wm_ = W_xi + m * HID;
            #pragma unroll 8
            for (int k = 0; k < HID; k++)
                acc = fmaf(g_hplain[b * HID + k], __ldg(&wm_[k]), acc);
            out[b * 64 + m] = acc;                  // zx: [B][64] at 0
            g_zxT[m * BATCH + b] = acc;
        } else if (bid < 80) {
            const int e = bid - 64;
            float acc = b_eta[e];
            const float* we = W_eta + e * HID;
            #pragma unroll 8
            for (int k = 0; k < HID; k++)
                acc = fmaf(g_hplain[b * HID + k], __ldg(&we[k]), acc);
            g_zeT[e * BATCH + b] = acc;
        }
    }
    arrive_wait(&g_fcnt, 256u, tid, lane);

    // Phase B: zy columns (blocks 0..63), ze softmax (block 64)
    if (b < BATCH) {
        if (bid < 64) {
            const int m = bid;
            float acc = b_zeta[m];
            const float* wz = W_zeta + m * (HID + 64);
            #pragma unroll 8
            for (int k = 0; k < HID; k++)
                acc = fmaf(g_hplain[b * HID + k], __ldg(&wz[k]), acc);
            #pragma unroll
            for (int j = 0; j < 64; j++)
                acc = fmaf(g_zxT[j * BATCH + b], __ldg(&wz[HID + j]), acc);
            out[16384 + b * 64 + m] = acc;          // zy: [B][64] at 16384
        } else if (bid == 64) {
            float l[16];
            float mx = -1e30f;
            #pragma unroll
            for (int e = 0; e < 16; e++) {
                l[e] = g_zeT[e * BATCH + b];
                mx = fmaxf(mx, l[e]);
            }
            float ssum = 0.0f;
            #pragma unroll
            for (int e = 0; e < 16; e++) { l[e] = __expf(l[e] - mx); ssum += l[e]; }
            float inv = __fdividef(1.0f, ssum);
            #pragma unroll
            for (int e = 0; e < 16; e++)
                out[32768 + b * 16 + e] = l[e] * inv;   // ze: [B][16] at 32768
        }
    }
}

// Reset barrier counters after each run so graph replays start from zero.
extern "C" __global__ void reset_counters() {
    int i = threadIdx.x;
    if (i < 128) g_gcnt4[i] = 0u;
    if (i == 128) g_fcnt = 0u;
}

extern "C" void kernel_launch(void* const* d_in, const int* in_sizes, int n_in,
                              void* d_out, int out_size) {
    const float* x      = (const float*)d_in[0];
    const float* a      = (const float*)d_in[1];
    const float* y      = (const float*)d_in[2];
    const float* W_ih   = (const float*)d_in[3];
    const float* W_hh   = (const float*)d_in[4];
    const float* b_ih   = (const float*)d_in[5];
    const float* b_hh   = (const float*)d_in[6];
    const float* W_eta  = (const float*)d_in[7];
    const float* b_eta  = (const float*)d_in[8];
    const float* W_xi   = (const float*)d_in[9];
    const float* b_xi   = (const float*)d_in[10];
    const float* W_zeta = (const float*)d_in[11];
    const float* b_zeta = (const float*)d_in[12];

    cudaFuncSetAttribute(lstm_persist,
                         cudaFuncAttributeMaxDynamicSharedMemorySize, SMEM_TOTAL);
    lstm_persist<<<NBLK, THREADS, SMEM_TOTAL>>>(
        x, a, y, W_ih, W_hh, b_ih, b_hh,
        W_eta, b_eta, W_xi, b_xi, W_zeta, b_zeta,
        (float*)d_out);
    reset_counters<<<1, 256>>>();
}

// round 13
// speedup vs baseline: 1.3943x; 1.0418x over previous
#include <cuda_runtime.h>
#include <cuda_bf16.h>

#define T_STEPS 1024
#define BATCH   256
#define HID     512
#define NBLK    128
#define THREADS 512

// 2D tiling: 4 batch-slices x 32 unit-slices
#define MB       64      // batches per block
#define NG       64      // gate columns per block (16 units x 4 gates)
#define UNITS    16

// W smem (k-major, proven layout)
#define WPITCH    72                          // bf16 per k-row (64 + 8 pad) = 144 B
#define WBYTES    (HID * WPITCH * 2)          // 73728 per W matrix
#define OFF_WHI   0
#define OFF_WLO   WBYTES
#define OFF_P     (2 * WBYTES)                // 147456 (params, 1 KB)
#define OFF_R     (OFF_P + 1024)              // 148480 (reduction buffer)
#define RED_BYTES (3 * 4 * 32 * 32 * 4)       // 49152
#define SMEM_TOTAL (OFF_R + RED_BYTES)        // 197632

// h in MMA A-fragment layout, hi and lo split (proven r12):
// [buf][mi][mt][kt][lane][8 bf16] -> 16B lane record; warp kt-load = 512B contig.
__device__ __nv_bfloat16 g_hfhi[2][4][4][32][32][8];   // 512 KB
__device__ __nv_bfloat16 g_hflo[2][4][4][32][32][8];   // 512 KB
__device__ float g_hplain[BATCH * HID];                // final h, fp32
__device__ float g_zxT[64 * BATCH];
__device__ float g_zeT[16 * BATCH];
__device__ unsigned int g_gc[4][128];      // [leaf][mi*32] spread group counters
__device__ unsigned int g_fcnt;            // full-grid monotonic counter

// ---------- helpers ----------
__device__ __forceinline__ unsigned s2u(const void* p) {
    unsigned r;
    asm("{ .reg .u64 t; cvta.to.shared.u64 t, %1; cvt.u32.u64 %0, t; }"
        : "=r"(r) : "l"(p));
    return r;
}

__device__ __forceinline__ void mma16816(float* d, const unsigned* a, const unsigned* b) {
    asm volatile(
        "mma.sync.aligned.m16n8k16.row.col.f32.bf16.bf16.f32 "
        "{%0,%1,%2,%3}, {%4,%5,%6,%7}, {%8,%9}, {%0,%1,%2,%3};"
        : "+f"(d[0]), "+f"(d[1]), "+f"(d[2]), "+f"(d[3])
        : "r"(a[0]), "r"(a[1]), "r"(a[2]), "r"(a[3]), "r"(b[0]), "r"(b[1]));
}

__device__ __forceinline__ void ldsm_x4t(unsigned* r, unsigned addr) {
    asm volatile("ldmatrix.sync.aligned.m8n8.x4.trans.shared.b16 {%0,%1,%2,%3}, [%4];"
                 : "=r"(r[0]), "=r"(r[1]), "=r"(r[2]), "=r"(r[3]) : "r"(addr));
}

__device__ __forceinline__ float sigf(float v) {
    return __fdividef(1.0f, 1.0f + __expf(-v));
}
__device__ __forceinline__ float tanh_fast(float v) {
    return __fdividef(2.0f, 1.0f + __expf(-2.0f * v)) - 1.0f;
}

// Spread group barrier: 4 leaf counters (8 arrivals each), parallel 4-lane poll.
__device__ __forceinline__ void gsyncG(int mi, int ni, unsigned gep,
                                       int tid, int lane) {
    __syncthreads();
    if (tid == 0) {
        __threadfence();
        asm volatile("red.release.gpu.global.add.u32 [%0], 1;"
                     :: "l"(&g_gc[ni & 3][mi << 5]) : "memory");
    }
    const unsigned target = 8u * gep;
    bool pend = (lane < 4);
    unsigned int* addr = &g_gc[lane & 3][mi << 5];
    while (__any_sync(0xffffffffu, pend)) {
        if (pend) {
            unsigned v;
            asm volatile("ld.acquire.gpu.global.u32 %0, [%1];"
                         : "=r"(v) : "l"(addr) : "memory");
            pend = (v < target);
        }
    }
    __syncwarp();
}

// Full-grid monotonic barrier (3 uses at end; single counter fine).
__device__ __forceinline__ void arrive_wait(unsigned int* cnt, unsigned target,
                                            int tid, int lane) {
    __syncthreads();
    if (tid == 0) {
        __threadfence();
        asm volatile("red.release.gpu.global.add.u32 [%0], 1;"
                     :: "l"(cnt) : "memory");
    }
    if (lane == 0) {
        unsigned v;
        do {
            asm volatile("ld.acquire.gpu.global.u32 %0, [%1];"
                         : "=r"(v) : "l"(cnt) : "memory");
        } while (v < target);
    }
    __syncwarp();
}

// ---------- main persistent kernel ----------
extern "C" __global__ void __launch_bounds__(THREADS, 1)
lstm_persist(const float* __restrict__ x, const float* __restrict__ a,
             const float* __restrict__ y,
             const float* __restrict__ W_ih, const float* __restrict__ W_hh,
             const float* __restrict__ b_ih, const float* __restrict__ b_hh,
             const float* __restrict__ W_eta, const float* __restrict__ b_eta,
             const float* __restrict__ W_xi,  const float* __restrict__ b_xi,
             const float* __restrict__ W_zeta, const float* __restrict__ b_zeta,
             float* __restrict__ out) {
    extern __shared__ char smem[];
    __nv_bfloat16* sWhi = (__nv_bfloat16*)(smem + OFF_WHI);
    __nv_bfloat16* sWlo = (__nv_bfloat16*)(smem + OFF_WLO);
    float* swx = (float*)(smem + OFF_P);
    float* swa = swx + 64;
    float* swy = swx + 128;
    float* sbb = swx + 192;
    float* sred = (float*)(smem + OFF_R);   // [slot 3][wm 4][reg 32][lane 32]
    const unsigned sb = s2u(smem);

    const int tid  = threadIdx.x;
    const int lane = tid & 31;
    const int w    = tid >> 5;       // 16 warps
    const int bid  = blockIdx.x;
    const int mi   = bid >> 5;       // batch slice 0..3
    const int ni   = bid & 31;       // unit slice 0..31
    const int wm   = w & 3;          // m-tile (== SMSP id)
    const int kq   = w >> 2;         // kt quarter 0..3

    unsigned gep = 0;

    // ---- W tile into smem, K-MAJOR (proven layout) ----
    for (int idx = tid; idx < NG * HID; idx += THREADS) {
        int j = idx >> 9, k = idx & 511;
        int row = (j & 3) * HID + ni * UNITS + (j >> 2);
        float v = W_hh[row * HID + k];
        __nv_bfloat16 hi = __float2bfloat16(v);
        sWhi[k * WPITCH + j] = hi;
        sWlo[k * WPITCH + j] = __float2bfloat16(v - __bfloat162float(hi));
    }
    if (tid < NG) {
        int row = (tid & 3) * HID + ni * UNITS + (tid >> 2);
        swx[tid] = W_ih[row * 3 + 0];
        swa[tid] = W_ih[row * 3 + 1];
        swy[tid] = W_ih[row * 3 + 2];
        sbb[tid] = b_ih[row] + b_hh[row];
    }

    // ---- zero fragment buffer 0 for our batch slice (group-cooperative) ----
    {
        uint4 z = make_uint4(0u, 0u, 0u, 0u);
        uint4* Zh = (uint4*)(&g_hfhi[0][mi][0][0][0][0]);   // 4096 uint4
        uint4* Zl = (uint4*)(&g_hflo[0][mi][0][0][0][0]);
        for (int i = ni * THREADS + tid; i < 4096; i += 32 * THREADS) {
            Zh[i] = z;
            Zl[i] = z;
        }
    }
    gsyncG(mi, ni, ++gep, tid, lane);

    // epilogue ownership (kq==0 warps only; one per SMSP)
    const bool act = ((lane & 1) == 0);
    const int qr  = lane >> 2;              // 0..7
    const int hb  = (lane & 3) >> 1;        // unit low bit
    const int r0  = 16 * wm + qr;
    const int b0g = mi * MB + r0;
    const int b1g = b0g + 8;
    float cst[8][2];
    #pragma unroll
    for (int i = 0; i < 8; i++) { cst[i][0] = 0.f; cst[i][1] = 0.f; }

    // B ldmatrix base: n-group 0 cols; +32B per n-group of 16 cols
    const unsigned bbase = (unsigned)((lane & 15) * (WPITCH * 2)
                                      + ((lane >> 4) & 1) * 16);

    int cur = 0;
    for (int s = 0; s < T_STEPS; s++) {
        const int t = T_STEPS - 1 - s;

        // A fragments for this warp's kt quarter, straight from global.
        const uint4* Ah = (const uint4*)(&g_hfhi[cur][mi][wm][kq * 8][lane][0]);
        const uint4* Al = (const uint4*)(&g_hflo[cur][mi][wm][kq * 8][lane][0]);

        // depth-2 prefetch ring over 8 kt
        uint4 rh[2], rl[2];
        rh[0] = __ldcg(Ah);      rl[0] = __ldcg(Al);
        rh[1] = __ldcg(Ah + 32); rl[1] = __ldcg(Al + 32);

        float x0, a0, y0, x1, a1, y1;
        if (kq == 0) {
            x0 = __ldg(&x[t * BATCH + b0g]);
            a0 = __ldg(&a[t * BATCH + b0g]);
            y0 = __ldg(&y[t * BATCH + b0g]);
            x1 = __ldg(&x[t * BATCH + b1g]);
            a1 = __ldg(&a[t * BATCH + b1g]);
            y1 = __ldg(&y[t * BATCH + b1g]);
        }

        float acc[8][4];
        #pragma unroll
        for (int i = 0; i < 8; i++)
            #pragma unroll
            for (int jj = 0; jj < 4; jj++) acc[i][jj] = 0.f;

        #pragma unroll
        for (int kl = 0; kl < 8; kl++) {
            const int kt = kq * 8 + kl;
            const int slot = kl & 1;
            unsigned ahi[4], alo[4];
            { uint4 v = rh[slot]; ahi[0]=v.x; ahi[1]=v.y; ahi[2]=v.z; ahi[3]=v.w; }
            { uint4 v = rl[slot]; alo[0]=v.x; alo[1]=v.y; alo[2]=v.z; alo[3]=v.w; }
            if (kl + 2 < 8) {
                rh[slot] = __ldcg(Ah + (kl + 2) * 32);
                rl[slot] = __ldcg(Al + (kl + 2) * 32);
            }

            const unsigned krow = (unsigned)(kt * (16 * WPITCH * 2));
            #pragma unroll
            for (int ng = 0; ng < 4; ng++) {
                unsigned bhi[4], blo[4];
                const unsigned boff = krow + bbase + (unsigned)(ng * 32);
                ldsm_x4t(bhi, sb + OFF_WHI + boff);
                ldsm_x4t(blo, sb + OFF_WLO + boff);
                mma16816(acc[2*ng],     ahi, bhi + 0);
                mma16816(acc[2*ng + 1], ahi, bhi + 2);
                mma16816(acc[2*ng],     ahi, blo + 0);
                mma16816(acc[2*ng + 1], ahi, blo + 2);
                mma16816(acc[2*ng],     alo, bhi + 0);
                mma16816(acc[2*ng + 1], alo, bhi + 2);
            }
        }

        // ---- cross-kq reduction through smem (conflict-free) ----
        if (kq != 0) {
            float* dst = sred + ((kq - 1) * 4 + wm) * (32 * 32) + lane;
            #pragma unroll
            for (int r = 0; r < 32; r++) dst[r * 32] = acc[r >> 2][r & 3];
        }
        __syncthreads();

        if (kq == 0) {
            #pragma unroll
            for (int sl = 0; sl < 3; sl++) {
                const float* src = sred + (sl * 4 + wm) * (32 * 32) + lane;
                #pragma unroll
                for (int r = 0; r < 32; r++) acc[r >> 2][r & 3] += src[r * 32];
            }

            // xproj add
            #pragma unroll
            for (int n8 = 0; n8 < 8; n8++) {
                int ce = n8 * 8 + 2 * (lane & 3);
                int co = ce + 1;
                float wxe = swx[ce], wae = swa[ce], wye = swy[ce], bbe = sbb[ce];
                float wxo = swx[co], wao = swa[co], wyo = swy[co], bbo = sbb[co];
                acc[n8][0] += fmaf(wxe, x0, fmaf(wae, a0, fmaf(wye, y0, bbe)));
                acc[n8][1] += fmaf(wxo, x0, fmaf(wao, a0, fmaf(wyo, y0, bbo)));
                acc[n8][2] += fmaf(wxe, x1, fmaf(wae, a1, fmaf(wye, y1, bbe)));
                acc[n8][3] += fmaf(wxo, x1, fmaf(wao, a1, fmaf(wyo, y1, bbo)));
            }

            // gates + fragment h store
            char* Hh = (char*)(&g_hfhi[cur ^ 1][mi][wm][ni][0][0]);
            char* Hl = (char*)(&g_hflo[cur ^ 1][mi][wm][ni][0][0]);
            #pragma unroll
            for (int n8 = 0; n8 < 8; n8++) {
                float gg[4];
                #pragma unroll
                for (int i = 0; i < 4; i++)
                    gg[i] = __shfl_xor_sync(0xffffffffu, acc[n8][i], 1);
                if (act) {
                    const int flane = qr * 4 + (n8 & 3);
                    const int regbase = 2 * (n8 >> 2);
                    #pragma unroll
                    for (int rr = 0; rr < 2; rr++) {
                        float iv = acc[n8][2 * rr + 0];
                        float fv = acc[n8][2 * rr + 1];
                        float gv = gg[2 * rr + 0];
                        float ov = gg[2 * rr + 1];
                        float cn = sigf(fv) * cst[n8][rr] + sigf(iv) * tanh_fast(gv);
                        cst[n8][rr] = cn;
                        float h = sigf(ov) * tanh_fast(cn);
                        unsigned off = (unsigned)(flane * 16 + (regbase + rr) * 4 + hb * 2);
                        __nv_bfloat16 hh = __float2bfloat16(h);
                        *(__nv_bfloat16*)(Hh + off) = hh;
                        *(__nv_bfloat16*)(Hl + off) =
                            __float2bfloat16(h - __bfloat162float(hh));
                        if (s == T_STEPS - 1) {
                            int kg = ni * UNITS + 2 * n8 + hb;
                            int bg = rr ? b1g : b0g;
                            g_hplain[bg * HID + kg] = h;
                        }
                    }
                }
            }
        }
        gsyncG(mi, ni, ++gep, tid, lane);
        cur ^= 1;
    }

    // all four groups done before heads read full h
    arrive_wait(&g_fcnt, 128u, tid, lane);

    const int b = tid;

    // Phase A: zx columns (blocks 0..63), ze logits (blocks 64..79)
    if (b < BATCH) {
        if (bid < 64) {
            const int m = bid;
            float acc = b_xi[m];
            const float* wm_ = W_xi + m * HID;
            #pragma unroll 8
            for (int k = 0; k < HID; k++)
                acc = fmaf(g_hplain[b * HID + k], __ldg(&wm_[k]), acc);
            out[b * 64 + m] = acc;                  // zx: [B][64] at 0
            g_zxT[m * BATCH + b] = acc;
        } else if (bid < 80) {
            const int e = bid - 64;
            float acc = b_eta[e];
            const float* we = W_eta + e * HID;
            #pragma unroll 8
            for (int k = 0; k < HID; k++)
                acc = fmaf(g_hplain[b * HID + k], __ldg(&we[k]), acc);
            g_zeT[e * BATCH + b] = acc;
        }
    }
    arrive_wait(&g_fcnt, 256u, tid, lane);

    // Phase B: zy columns (blocks 0..63), ze softmax (block 64)
    if (b < BATCH) {
        if (bid < 64) {
            const int m = bid;
            float acc = b_zeta[m];
            const float* wz = W_zeta + m * (HID + 64);
            #pragma unroll 8
            for (int k = 0; k < HID; k++)
                acc = fmaf(g_hplain[b * HID + k], __ldg(&wz[k]), acc);
            #pragma unroll
            for (int j = 0; j < 64; j++)
                acc = fmaf(g_zxT[j * BATCH + b], __ldg(&wz[HID + j]), acc);
            out[16384 + b * 64 + m] = acc;          // zy: [B][64] at 16384
        } else if (bid == 64) {
            float l[16];
            float mx = -1e30f;
            #pragma unroll
            for (int e = 0; e < 16; e++) {
                l[e] = g_zeT[e * BATCH + b];
                mx = fmaxf(mx, l[e]);
            }
            float ssum = 0.0f;
            #pragma unroll
            for (int e = 0; e < 16; e++) { l[e] = __expf(l[e] - mx); ssum += l[e]; }
            float inv = __fdividef(1.0f, ssum);
            #pragma unroll
            for (int e = 0; e < 16; e++)
                out[32768 + b * 16 + e] = l[e] * inv;   // ze: [B][16] at 32768
        }
    }
}

// Reset barrier counters after each run so graph replays start from zero.
extern "C" __global__ void reset_counters() {
    int i = threadIdx.x;
    if (i < 512) ((unsigned int*)g_gc)[i] = 0u;
    if (i == 0) g_fcnt = 0u;
}

extern "C" void kernel_launch(void* const* d_in, const int* in_sizes, int n_in,
                              void* d_out, int out_size) {
    const float* x      = (const float*)d_in[0];
    const float* a      = (const float*)d_in[1];
    const float* y      = (const float*)d_in[2];
    const float* W_ih   = (const float*)d_in[3];
    const float* W_hh   = (const float*)d_in[4];
    const float* b_ih   = (const float*)d_in[5];
    const float* b_hh   = (const float*)d_in[6];
    const float* W_eta  = (const float*)d_in[7];
    const float* b_eta  = (const float*)d_in[8];
    const float* W_xi   = (const float*)d_in[9];
    const float* b_xi   = (const float*)d_in[10];
    const float* W_zeta = (const float*)d_in[11];
    const float* b_zeta = (const float*)d_in[12];

    cudaFuncSetAttribute(lstm_persist,
                         cudaFuncAttributeMaxDynamicSharedMemorySize, SMEM_TOTAL);
    lstm_persist<<<NBLK, THREADS, SMEM_TOTAL>>>(
        x, a, y, W_ih, W_hh, b_ih, b_hh,
        W_eta, b_eta, W_xi, b_xi, W_zeta, b_zeta,
        (float*)d_out);
    reset_counters<<<1, 512>>>();
}